// round 15
// baseline (speedup 1.0000x reference)
#include <cuda_runtime.h>
#include <cuda_fp16.h>
#include <mma.h>
#include <cstdint>

using namespace nvcuda;

#define BATCH  16384
#define HDIM   1024
#define KTOT   2048
#define WROWS  5120          // 5 gates * 1024
#define BM     128           // batch rows per CTA
#define HB     32            // h columns per CTA
#define NG     160           // 5 gates * HB
#define BK     32            // K per stage
#define NCHUNK (KTOT / BK)   // 64
#define LDSLD  40            // fp16 leading dim: 80B pitch, conflict-free LDSM
#define NSTAGE 4
#define NTHREADS 256

// Stage layout (bytes): A [128][40] fp16 = 10240, B [160][40] fp16 = 12800
#define A_OFF 0
#define B_OFF 10240
#define STAGE 23040
#define GLD   164            // gates smem row stride (floats): 160 + 4 pad
#define BSUM_OFF (NSTAGE * STAGE)         // 92160 (gates reuse: 128*164*4 = 83968 fits below)
#define SMEM_REQ (BSUM_OFF + 1024)        // 93184 -> 2 CTAs = 186368 <= 227KB

// Preprocessed fp16 operands (static device scratch, 84 MB)
__device__ __half g_Ah[(size_t)BATCH * KTOT];
__device__ __half g_Wh[(size_t)WROWS * KTOT];

__device__ __forceinline__ float sigmoidf_fast(float v) { return 1.0f / (1.0f + __expf(-v)); }
__device__ __forceinline__ uint32_t smem_u32(const void* p) {
    uint32_t a;
    asm("{ .reg .u64 t; cvta.to.shared.u64 t, %1; cvt.u32.u64 %0, t; }" : "=r"(a) : "l"(p));
    return a;
}
__device__ __forceinline__ void cpasync16(uint32_t dst, const void* src) {
    asm volatile("cp.async.cg.shared.global [%0], [%1], 16;" :: "r"(dst), "l"(src));
}
__device__ __forceinline__ void cp_commit() { asm volatile("cp.async.commit_group;" ::: "memory"); }
__device__ __forceinline__ void cp_wait2() { asm volatile("cp.async.wait_group 2;" ::: "memory"); }

// ---------------------------------------------------------------------------
// Preprocess: fp32 -> fp16.  A[16384][2048] = [x|h_prev], W[5120][2048] = [Wx|Uh]
// ---------------------------------------------------------------------------
__global__ __launch_bounds__(256)
void preprocess_kernel(const float* __restrict__ x, const float* __restrict__ h,
                       const float* __restrict__ Wx, const float* __restrict__ Uh)
{
    const size_t A_UNITS = (size_t)BATCH * KTOT / 8;   // 4194304
    const size_t W_UNITS = (size_t)WROWS * KTOT / 8;   // 1310720
    size_t u = (size_t)blockIdx.x * 256 + threadIdx.x;
    if (u >= A_UNITS + W_UNITS) return;

    const float* src;
    __half* dst;
    if (u < A_UNITS) {
        size_t row = u >> 8, col = (u & 255) * 8;
        src = (col < 1024) ? x + row * 1024 + col : h + row * 1024 + (col - 1024);
        dst = g_Ah + row * KTOT + col;
    } else {
        size_t v = u - A_UNITS;
        size_t row = v >> 8, col = (v & 255) * 8;
        src = (col < 1024) ? Wx + row * 1024 + col : Uh + row * 1024 + (col - 1024);
        dst = g_Wh + row * KTOT + col;
    }
    float4 f0 = *(const float4*)src;
    float4 f1 = *(const float4*)(src + 4);
    __half2 o[4];
    o[0] = __floats2half2_rn(f0.x, f0.y);
    o[1] = __floats2half2_rn(f0.z, f0.w);
    o[2] = __floats2half2_rn(f1.x, f1.y);
    o[3] = __floats2half2_rn(f1.z, f1.w);
    *(uint4*)dst = *(uint4*)o;
}

// ---------------------------------------------------------------------------
// GEMM (fp16 single-pass, fp32 acc) + fused LSTM epilogue.
// 256 threads, 2 CTAs/SM. Warp grid 4(m) x 2(n); warp tile 32 x 80 -> acc[2][5].
// 4-stage cp.async ring; hoisted pointer state; issue-before-mma.
// ---------------------------------------------------------------------------
__global__ __launch_bounds__(NTHREADS, 2)
void lstm_mma_kernel(const float* __restrict__ c_prev, const float* __restrict__ dw,
                     const float* __restrict__ bx, const float* __restrict__ bh,
                     float* __restrict__ out)
{
    extern __shared__ char sm[];
    const int tid  = threadIdx.x;
    const int warp = tid >> 5;
    const int m0 = blockIdx.y * BM;
    const int h0 = blockIdx.x * HB;
    const uint32_t smb = smem_u32(sm);

    const int wm = (warp & 3) * 32;     // 0..96
    const int wn = (warp >> 2) * 80;    // 0 or 80

    wmma::fragment<wmma::accumulator, 16, 16, 16, float> acc[2][5];
    #pragma unroll
    for (int i = 0; i < 2; i++)
        #pragma unroll
        for (int j = 0; j < 5; j++) wmma::fill_fragment(acc[i][j], 0.0f);

    // ---- hoisted per-thread loader state -----------------------------------
    const int seg  = tid & 3;                 // 16B unit within a row
    const int rA0  = tid >> 2;                // A rows (two passes)
    const int rA1  = (tid + 256) >> 2;
    const int rB0  = tid >> 2;                // B rows (three passes, last half-width)
    const int rB1  = (tid + 256) >> 2;
    const int rB2  = (tid + 512) >> 2;        // valid only for tid < 128

    const __half* pA0 = g_Ah + (size_t)(m0 + rA0) * KTOT + seg * 8;
    const __half* pA1 = g_Ah + (size_t)(m0 + rA1) * KTOT + seg * 8;
    const __half* pB0 = g_Wh + (size_t)((rB0 >> 5) * 1024 + h0 + (rB0 & 31)) * KTOT + seg * 8;
    const __half* pB1 = g_Wh + (size_t)((rB1 >> 5) * 1024 + h0 + (rB1 & 31)) * KTOT + seg * 8;
    const __half* pB2 = g_Wh + (size_t)(((rB2 >> 5) & 7) * 1024 + h0 + (rB2 & 31)) * KTOT + seg * 8;

    const uint32_t oA0 = A_OFF + rA0 * 80 + seg * 16;
    const uint32_t oA1 = A_OFF + rA1 * 80 + seg * 16;
    const uint32_t oB0 = B_OFF + rB0 * 80 + seg * 16;
    const uint32_t oB1 = B_OFF + rB1 * 80 + seg * 16;
    const uint32_t oB2 = B_OFF + rB2 * 80 + seg * 16;
    const bool b2ok = (tid < 128);

    auto issue5 = [&](uint32_t base) {
        cpasync16(base + oA0, pA0);
        cpasync16(base + oA1, pA1);
        cpasync16(base + oB0, pB0);
        cpasync16(base + oB1, pB1);
        if (b2ok) cpasync16(base + oB2, pB2);
        pA0 += BK; pA1 += BK; pB0 += BK; pB1 += BK; pB2 += BK;
    };

    // Prologue: stages 0..2 in flight.
    #pragma unroll
    for (int c = 0; c < 3; c++) { issue5(smb + c * STAGE); cp_commit(); }

    for (int i = 0; i < NCHUNK; i++) {
        cp_wait2();            // stage i landed
        __syncthreads();

        // Issue stage i+3 FIRST so its LDGs overlap the whole mma block.
        if (i + 3 < NCHUNK) issue5(smb + ((i + 3) & (NSTAGE - 1)) * STAGE);
        cp_commit();

        const char* st = sm + (i & (NSTAGE - 1)) * STAGE;
        const __half* Ah = (const __half*)(st + A_OFF);
        const __half* Bh = (const __half*)(st + B_OFF);

        #pragma unroll
        for (int ks = 0; ks < BK; ks += 16) {
            wmma::fragment<wmma::matrix_a, 16, 16, 16, __half, wmma::row_major> ahf[2];
            #pragma unroll
            for (int i2 = 0; i2 < 2; i2++)
                wmma::load_matrix_sync(ahf[i2], Ah + (wm + i2 * 16) * LDSLD + ks, LDSLD);
            #pragma unroll
            for (int j = 0; j < 5; j++) {
                wmma::fragment<wmma::matrix_b, 16, 16, 16, __half, wmma::col_major> bhf;
                wmma::load_matrix_sync(bhf, Bh + (wn + j * 16) * LDSLD + ks, LDSLD);
                #pragma unroll
                for (int i2 = 0; i2 < 2; i2++)
                    wmma::mma_sync(acc[i2][j], ahf[i2], bhf, acc[i2][j]);
            }
        }
    }
    __syncthreads();           // all fragment loads done before smem reuse

    // ---- stage gates in smem ----------------------------------------------
    float* gates = (float*)sm;                 // [128][GLD]
    float* bsum  = (float*)(sm + BSUM_OFF);    // [160]
    #pragma unroll
    for (int i2 = 0; i2 < 2; i2++)
        #pragma unroll
        for (int j = 0; j < 5; j++)
            wmma::store_matrix_sync(gates + (wm + i2 * 16) * GLD + wn + j * 16, acc[i2][j],
                                    GLD, wmma::mem_row_major);
    if (tid < NG) {
        int g = tid >> 5, c = tid & 31;
        int gi = g * 1024 + h0 + c;
        bsum[tid] = bx[gi] + bh[gi];
    }
    __syncthreads();

    // ---- fused LSTM epilogue: 128*32 elems, 16/thread ----------------------
    #pragma unroll
    for (int p = 0; p < 16; p++) {
        int lin = p * NTHREADS + tid;
        int r = lin >> 5;                // 0..127
        int c = lin & 31;                // 0..31
        size_t gidx = (size_t)(m0 + r) * 1024 + h0 + c;
        const float* gr = gates + r * GLD;

        float gi_ = gr[c]        + bsum[c];
        float gf_ = gr[32 + c]   + bsum[32 + c];
        float go_ = gr[64 + c]   + bsum[64 + c];
        float gc_ = gr[96 + c]   + bsum[96 + c];
        float gs_ = gr[128 + c]  + bsum[128 + c];

        float i_t   = sigmoidf_fast(gi_);
        float f_t   = sigmoidf_fast(gf_);
        float o_t   = sigmoidf_fast(go_);
        float c_hat = tanhf(gc_);
        float s_t   = sigmoidf_fast(gs_) * dw[gidx];

        float c_t = f_t * c_prev[gidx] + i_t * c_hat * s_t;
        float h_t = o_t * tanhf(c_t);

        out[gidx] = h_t;
        out[(size_t)BATCH * HDIM + gidx] = c_t;
    }
}

// ---------------------------------------------------------------------------
// Inputs (metadata order): x, h_prev, c_prev, dynamic_weight, Wx, bx, Uh, bh
// ---------------------------------------------------------------------------
extern "C" void kernel_launch(void* const* d_in, const int* in_sizes, int n_in,
                              void* d_out, int out_size)
{
    const float* x  = (const float*)d_in[0];
    const float* hp = (const float*)d_in[1];
    const float* cp = (const float*)d_in[2];
    const float* dw = (const float*)d_in[3];
    const float* Wx = (const float*)d_in[4];
    const float* bx = (const float*)d_in[5];
    const float* Uh = (const float*)d_in[6];
    const float* bh = (const float*)d_in[7];
    float* out = (float*)d_out;

    const size_t total_units = (size_t)BATCH * KTOT / 8 + (size_t)WROWS * KTOT / 8;
    preprocess_kernel<<<(unsigned)((total_units + 255) / 256), 256>>>(x, hp, Wx, Uh);

    cudaFuncSetAttribute(lstm_mma_kernel,
                         cudaFuncAttributeMaxDynamicSharedMemorySize, SMEM_REQ);
    dim3 grid(HDIM / HB, BATCH / BM);   // (32, 128) = 4096 CTAs
    lstm_mma_kernel<<<grid, NTHREADS, SMEM_REQ>>>(cp, dw, bx, bh, out);
}

// round 16
// speedup vs baseline: 1.0780x; 1.0780x over previous
#include <cuda_runtime.h>
#include <cuda_fp16.h>
#include <mma.h>
#include <cstdint>

using namespace nvcuda;

#define BATCH  16384
#define HDIM   1024
#define KTOT   2048
#define WROWS  5120          // 5 gates * 1024
#define BM     128           // batch rows per CTA
#define HB     32            // h columns per CTA
#define NG     160           // 5 gates * HB
#define BK     32            // K per stage
#define NCHUNK (KTOT / BK)   // 64
#define LDSLD  40            // fp16 leading dim: 80B pitch, conflict-free LDSM
#define NSTAGE 4
#define NTHREADS 256

// Stage layout (bytes): A [128][40] fp16 = 10240, B [160][40] fp16 = 12800
#define A_OFF 0
#define B_OFF 10240
#define STAGE 23040
#define GLD   164            // gates smem row stride (floats): 160 + 4 pad
#define BSUM_OFF (NSTAGE * STAGE)         // 92160 (gates reuse: 128*164*4 = 83968 fits below)
#define SMEM_REQ (BSUM_OFF + 1024)        // 93184 -> 2 CTAs = 186368 <= 227KB

// Preprocessed fp16 operands (static device scratch, 84 MB)
__device__ __half g_Ah[(size_t)BATCH * KTOT];
__device__ __half g_Wh[(size_t)WROWS * KTOT];

__device__ __forceinline__ float sigmoidf_fast(float v) { return 1.0f / (1.0f + __expf(-v)); }
__device__ __forceinline__ uint32_t smem_u32(const void* p) {
    uint32_t a;
    asm("{ .reg .u64 t; cvta.to.shared.u64 t, %1; cvt.u32.u64 %0, t; }" : "=r"(a) : "l"(p));
    return a;
}
__device__ __forceinline__ void cpasync16(uint32_t dst, const void* src) {
    asm volatile("cp.async.cg.shared.global [%0], [%1], 16;" :: "r"(dst), "l"(src));
}
__device__ __forceinline__ void cp_commit() { asm volatile("cp.async.commit_group;" ::: "memory"); }
__device__ __forceinline__ void cp_wait2() { asm volatile("cp.async.wait_group 2;" ::: "memory"); }

// ---------------------------------------------------------------------------
// Preprocess: fp32 -> fp16.  A[16384][2048] = [x|h_prev], W[5120][2048] = [Wx|Uh]
// ---------------------------------------------------------------------------
__global__ __launch_bounds__(256)
void preprocess_kernel(const float* __restrict__ x, const float* __restrict__ h,
                       const float* __restrict__ Wx, const float* __restrict__ Uh)
{
    const size_t A_UNITS = (size_t)BATCH * KTOT / 8;   // 4194304
    const size_t W_UNITS = (size_t)WROWS * KTOT / 8;   // 1310720
    size_t u = (size_t)blockIdx.x * 256 + threadIdx.x;
    if (u >= A_UNITS + W_UNITS) return;

    const float* src;
    __half* dst;
    if (u < A_UNITS) {
        size_t row = u >> 8, col = (u & 255) * 8;
        src = (col < 1024) ? x + row * 1024 + col : h + row * 1024 + (col - 1024);
        dst = g_Ah + row * KTOT + col;
    } else {
        size_t v = u - A_UNITS;
        size_t row = v >> 8, col = (v & 255) * 8;
        src = (col < 1024) ? Wx + row * 1024 + col : Uh + row * 1024 + (col - 1024);
        dst = g_Wh + row * KTOT + col;
    }
    float4 f0 = *(const float4*)src;
    float4 f1 = *(const float4*)(src + 4);
    __half2 o[4];
    o[0] = __floats2half2_rn(f0.x, f0.y);
    o[1] = __floats2half2_rn(f0.z, f0.w);
    o[2] = __floats2half2_rn(f1.x, f1.y);
    o[3] = __floats2half2_rn(f1.z, f1.w);
    *(uint4*)dst = *(uint4*)o;
}

// ---------------------------------------------------------------------------
// GEMM (fp16 single-pass, fp32 acc) + fused LSTM epilogue.
// 256 threads, 2 CTAs/SM. Warp grid 4(m) x 2(n); warp tile 32 x 80 -> acc[2][5].
// 4-stage cp.async ring; R14 issue placement (after mma); hoisted pointers only.
// ---------------------------------------------------------------------------
__global__ __launch_bounds__(NTHREADS, 2)
void lstm_mma_kernel(const float* __restrict__ c_prev, const float* __restrict__ dw,
                     const float* __restrict__ bx, const float* __restrict__ bh,
                     float* __restrict__ out)
{
    extern __shared__ char sm[];
    const int tid  = threadIdx.x;
    const int warp = tid >> 5;
    const int m0 = blockIdx.y * BM;
    const int h0 = blockIdx.x * HB;
    const uint32_t smb = smem_u32(sm);

    const int wm = (warp & 3) * 32;     // 0..96
    const int wn = (warp >> 2) * 80;    // 0 or 80

    wmma::fragment<wmma::accumulator, 16, 16, 16, float> acc[2][5];
    #pragma unroll
    for (int i = 0; i < 2; i++)
        #pragma unroll
        for (int j = 0; j < 5; j++) wmma::fill_fragment(acc[i][j], 0.0f);

    // ---- hoisted per-thread loader state -----------------------------------
    const int seg  = tid & 3;                 // 16B unit within a row
    const int rA0  = tid >> 2;                // A rows (two passes)
    const int rA1  = (tid + 256) >> 2;
    const int rB0  = tid >> 2;                // B rows (three passes, last half-width)
    const int rB1  = (tid + 256) >> 2;
    const int rB2  = (tid + 512) >> 2;        // valid only for tid < 128

    const __half* pA0 = g_Ah + (size_t)(m0 + rA0) * KTOT + seg * 8;
    const __half* pA1 = g_Ah + (size_t)(m0 + rA1) * KTOT + seg * 8;
    const __half* pB0 = g_Wh + (size_t)((rB0 >> 5) * 1024 + h0 + (rB0 & 31)) * KTOT + seg * 8;
    const __half* pB1 = g_Wh + (size_t)((rB1 >> 5) * 1024 + h0 + (rB1 & 31)) * KTOT + seg * 8;
    const __half* pB2 = g_Wh + (size_t)(((rB2 >> 5) & 7) * 1024 + h0 + (rB2 & 31)) * KTOT + seg * 8;

    const uint32_t oA0 = A_OFF + rA0 * 80 + seg * 16;
    const uint32_t oA1 = A_OFF + rA1 * 80 + seg * 16;
    const uint32_t oB0 = B_OFF + rB0 * 80 + seg * 16;
    const uint32_t oB1 = B_OFF + rB1 * 80 + seg * 16;
    const uint32_t oB2 = B_OFF + rB2 * 80 + seg * 16;
    const bool b2ok = (tid < 128);

    auto issue5 = [&](uint32_t base) {
        cpasync16(base + oA0, pA0);
        cpasync16(base + oA1, pA1);
        cpasync16(base + oB0, pB0);
        cpasync16(base + oB1, pB1);
        if (b2ok) cpasync16(base + oB2, pB2);
        pA0 += BK; pA1 += BK; pB0 += BK; pB1 += BK; pB2 += BK;
    };

    // Prologue: stages 0..2 in flight.
    #pragma unroll
    for (int c = 0; c < 3; c++) { issue5(smb + c * STAGE); cp_commit(); }

    for (int i = 0; i < NCHUNK; i++) {
        cp_wait2();            // stage i landed
        __syncthreads();

        const char* st = sm + (i & (NSTAGE - 1)) * STAGE;
        const __half* Ah = (const __half*)(st + A_OFF);
        const __half* Bh = (const __half*)(st + B_OFF);

        #pragma unroll
        for (int ks = 0; ks < BK; ks += 16) {
            wmma::fragment<wmma::matrix_a, 16, 16, 16, __half, wmma::row_major> ahf[2];
            #pragma unroll
            for (int i2 = 0; i2 < 2; i2++)
                wmma::load_matrix_sync(ahf[i2], Ah + (wm + i2 * 16) * LDSLD + ks, LDSLD);
            #pragma unroll
            for (int j = 0; j < 5; j++) {
                wmma::fragment<wmma::matrix_b, 16, 16, 16, __half, wmma::col_major> bhf;
                wmma::load_matrix_sync(bhf, Bh + (wn + j * 16) * LDSLD + ks, LDSLD);
                #pragma unroll
                for (int i2 = 0; i2 < 2; i2++)
                    wmma::mma_sync(acc[i2][j], ahf[i2], bhf, acc[i2][j]);
            }
        }
        if (i + 3 < NCHUNK) issue5(smb + ((i + 3) & (NSTAGE - 1)) * STAGE);
        cp_commit();
    }
    __syncthreads();           // all fragment loads done before smem reuse

    // ---- stage gates in smem ----------------------------------------------
    float* gates = (float*)sm;                 // [128][GLD]
    float* bsum  = (float*)(sm + BSUM_OFF);    // [160]
    #pragma unroll
    for (int i2 = 0; i2 < 2; i2++)
        #pragma unroll
        for (int j = 0; j < 5; j++)
            wmma::store_matrix_sync(gates + (wm + i2 * 16) * GLD + wn + j * 16, acc[i2][j],
                                    GLD, wmma::mem_row_major);
    if (tid < NG) {
        int g = tid >> 5, c = tid & 31;
        int gi = g * 1024 + h0 + c;
        bsum[tid] = bx[gi] + bh[gi];
    }
    __syncthreads();

    // ---- fused LSTM epilogue: 128*32 elems, 16/thread ----------------------
    #pragma unroll
    for (int p = 0; p < 16; p++) {
        int lin = p * NTHREADS + tid;
        int r = lin >> 5;                // 0..127
        int c = lin & 31;                // 0..31
        size_t gidx = (size_t)(m0 + r) * 1024 + h0 + c;
        const float* gr = gates + r * GLD;

        float gi_ = gr[c]        + bsum[c];
        float gf_ = gr[32 + c]   + bsum[32 + c];
        float go_ = gr[64 + c]   + bsum[64 + c];
        float gc_ = gr[96 + c]   + bsum[96 + c];
        float gs_ = gr[128 + c]  + bsum[128 + c];

        float i_t   = sigmoidf_fast(gi_);
        float f_t   = sigmoidf_fast(gf_);
        float o_t   = sigmoidf_fast(go_);
        float c_hat = tanhf(gc_);
        float s_t   = sigmoidf_fast(gs_) * dw[gidx];

        float c_t = f_t * c_prev[gidx] + i_t * c_hat * s_t;
        float h_t = o_t * tanhf(c_t);

        out[gidx] = h_t;
        out[(size_t)BATCH * HDIM + gidx] = c_t;
    }
}

// ---------------------------------------------------------------------------
// Inputs (metadata order): x, h_prev, c_prev, dynamic_weight, Wx, bx, Uh, bh
// ---------------------------------------------------------------------------
extern "C" void kernel_launch(void* const* d_in, const int* in_sizes, int n_in,
                              void* d_out, int out_size)
{
    const float* x  = (const float*)d_in[0];
    const float* hp = (const float*)d_in[1];
    const float* cp = (const float*)d_in[2];
    const float* dw = (const float*)d_in[3];
    const float* Wx = (const float*)d_in[4];
    const float* bx = (const float*)d_in[5];
    const float* Uh = (const float*)d_in[6];
    const float* bh = (const float*)d_in[7];
    float* out = (float*)d_out;

    const size_t total_units = (size_t)BATCH * KTOT / 8 + (size_t)WROWS * KTOT / 8;
    preprocess_kernel<<<(unsigned)((total_units + 255) / 256), 256>>>(x, hp, Wx, Uh);

    cudaFuncSetAttribute(lstm_mma_kernel,
                         cudaFuncAttributeMaxDynamicSharedMemorySize, SMEM_REQ);
    dim3 grid(HDIM / HB, BATCH / BM);   // (32, 128) = 4096 CTAs
    lstm_mma_kernel<<<grid, NTHREADS, SMEM_REQ>>>(cp, dw, bx, bh, out);
}